// round 9
// baseline (speedup 1.0000x reference)
#include <cuda_runtime.h>
#include <math.h>

#define Bsz   2048
#define Fdim  128
#define Hdim  512
#define Tlen  96
#define G3H   1536
#define Mtile 8
#define NTHREADS 256

typedef unsigned long long ull;

// Transposed weights (k-major) in device scratch, ~4MB, L2-resident.
__device__ __align__(16) float d_WhhT[Hdim * G3H];  // [k][n] k<512, n<1536
__device__ __align__(16) float d_WihT[Fdim * G3H];  // [k][n] k<128, n<1536
__device__ __align__(16) float d_FcwT[Hdim * Fdim]; // [k][f] k<512, f<128

// ---- packed f32x2 helpers ----
__device__ __forceinline__ ull bcast2(float a) {
    ull r; unsigned int u = __float_as_uint(a);
    asm("mov.b64 %0, {%1, %1};" : "=l"(r) : "r"(u));
    return r;
}
__device__ __forceinline__ void fma2(ull& d, ull a, ull b) {
    asm("fma.rn.f32x2 %0, %1, %2, %0;" : "+l"(d) : "l"(a), "l"(b));
}
__device__ __forceinline__ float2 unpack2(ull v) {
    unsigned int lo, hi;
    asm("mov.b64 {%0, %1}, %2;" : "=r"(lo), "=r"(hi) : "l"(v));
    return make_float2(__uint_as_float(lo), __uint_as_float(hi));
}
__device__ __forceinline__ ull ld64(const float* p) {
    return *reinterpret_cast<const ull*>(p);
}

// One-time weight transpose
__global__ void gru_setup_kernel(const float* __restrict__ w_ih,
                                 const float* __restrict__ w_hh,
                                 const float* __restrict__ fc_w) {
    int idx = blockIdx.x * blockDim.x + threadIdx.x;
    if (idx < Hdim * G3H) {
        int k = idx / G3H, n = idx - k * G3H;
        d_WhhT[idx] = w_hh[n * Hdim + k];
    }
    int i2 = idx - Hdim * G3H;
    if (i2 >= 0 && i2 < Fdim * G3H) {
        int k = i2 / G3H, n = i2 - k * G3H;
        d_WihT[i2] = w_ih[n * Fdim + k];
    }
    int i3 = idx - Hdim * G3H - Fdim * G3H;
    if (i3 >= 0 && i3 < Hdim * Fdim) {
        int k = i3 / Fdim, f = i3 - k * Fdim;
        d_FcwT[i3] = fc_w[f * Hdim + k];
    }
}

// ---- register double-buffered 3-gate GEMM slab ----
// Per-thread tile: 4 m-rows x 2 n-cols (1 packed ull) x 3 gates.
// Weight buffers: 4 k-steps x 3 gates, A/B ping-pong (48 regs).
template<int LD, int NIT>   // NIT = K/4, must be even
__device__ __forceinline__ void gemm3(
    const float* __restrict__ wbase,   // Wt + col (row k at wbase + k*G3H)
    const float* __restrict__ in,      // activations [m][LD] in smem
    int mrow0,
    ull (&aR)[4], ull (&aZ)[4], ull (&aX)[4])
{
    ull wA[4][3], wB[4][3];

    #pragma unroll
    for (int kk = 0; kk < 4; ++kk) {
        const float* w = wbase + (size_t)kk * G3H;
        wA[kk][0] = ld64(w); wA[kk][1] = ld64(w + 512); wA[kk][2] = ld64(w + 1024);
    }

    #pragma unroll 1
    for (int it = 0; it < NIT; it += 2) {
        // prefetch B <- stage it+1 (valid: NIT even)
        {
            const float* wr = wbase + (size_t)(it + 1) * 4 * G3H;
            #pragma unroll
            for (int kk = 0; kk < 4; ++kk) {
                const float* w = wr + (size_t)kk * G3H;
                wB[kk][0] = ld64(w); wB[kk][1] = ld64(w + 512); wB[kk][2] = ld64(w + 1024);
            }
        }
        // compute A @ stage it
        {
            const int k0 = it * 4;
            float4 av[4];
            #pragma unroll
            for (int i = 0; i < 4; ++i)
                av[i] = *reinterpret_cast<const float4*>(&in[(mrow0 + i) * LD + k0]);
            #pragma unroll
            for (int kk = 0; kk < 4; ++kk) {
                ull wr = wA[kk][0], wz = wA[kk][1], wn = wA[kk][2];
                #pragma unroll
                for (int i = 0; i < 4; ++i) {
                    ull a2 = bcast2(reinterpret_cast<const float*>(&av[i])[kk]);
                    fma2(aR[i], a2, wr);
                    fma2(aZ[i], a2, wz);
                    fma2(aX[i], a2, wn);
                }
            }
        }
        // prefetch A <- stage it+2 (clamped)
        {
            const int nx = (it + 2 < NIT) ? (it + 2) : it;
            const float* wr = wbase + (size_t)nx * 4 * G3H;
            #pragma unroll
            for (int kk = 0; kk < 4; ++kk) {
                const float* w = wr + (size_t)kk * G3H;
                wA[kk][0] = ld64(w); wA[kk][1] = ld64(w + 512); wA[kk][2] = ld64(w + 1024);
            }
        }
        // compute B @ stage it+1
        {
            const int k0 = (it + 1) * 4;
            float4 av[4];
            #pragma unroll
            for (int i = 0; i < 4; ++i)
                av[i] = *reinterpret_cast<const float4*>(&in[(mrow0 + i) * LD + k0]);
            #pragma unroll
            for (int kk = 0; kk < 4; ++kk) {
                ull wr = wB[kk][0], wz = wB[kk][1], wn = wB[kk][2];
                #pragma unroll
                for (int i = 0; i < 4; ++i) {
                    ull a2 = bcast2(reinterpret_cast<const float*>(&av[i])[kk]);
                    fma2(aR[i], a2, wr);
                    fma2(aZ[i], a2, wz);
                    fma2(aX[i], a2, wn);
                }
            }
        }
    }
}

__global__ __launch_bounds__(NTHREADS, 2)
void gru_kernel(const float* __restrict__ hidden,
                const float* __restrict__ b_ih,
                const float* __restrict__ b_hh,
                const float* __restrict__ fc_b,
                float* __restrict__ out) {
    extern __shared__ float smem[];
    float* hbufA = smem;                          // Mtile*Hdim
    float* hbufB = hbufA + Mtile * Hdim;          // Mtile*Hdim
    float* xbuf  = hbufB + Mtile * Hdim;          // Mtile*Fdim
    float* brz   = xbuf + Mtile * Fdim;           // 2*Hdim
    float* bin   = brz + 2 * Hdim;                // Hdim
    float* bhn   = bin + Hdim;                    // Hdim
    float* fcb   = bhn + Hdim;                    // Fdim

    const int tid = threadIdx.x;
    const int m0  = blockIdx.x * Mtile;

    for (int i = tid; i < Mtile * Hdim; i += NTHREADS) hbufA[i] = hidden[m0 * Hdim + i];
    for (int i = tid; i < Mtile * Fdim; i += NTHREADS) xbuf[i] = 0.f;
    for (int i = tid; i < 2 * Hdim; i += NTHREADS)     brz[i] = b_ih[i] + b_hh[i];
    for (int i = tid; i < Hdim; i += NTHREADS) {
        bin[i] = b_ih[2 * Hdim + i];
        bhn[i] = b_hh[2 * Hdim + i];
    }
    for (int i = tid; i < Fdim; i += NTHREADS)         fcb[i] = fc_b[i];
    __syncthreads();

    // Phase-1 mapping: 2 m-groups (4 rows) x 128 n-groups (2 cols);
    // 2 chunks of 256 n-cols per gate.
    const int mg    = tid >> 7;            // 0..1
    const int ng2   = (tid & 127) * 2;     // packed col pair within 256-chunk
    const int mrow0 = mg * 4;
    // Phase-2 mapping: 4 m-groups (2 rows) x 64 f-groups (2 cols)
    const int mh = tid >> 6;               // 0..3
    const int f0 = (tid & 63) * 2;

    float* hc = hbufA;
    float* hn = hbufB;

    for (int s = 0; s < Tlen; ++s) {
        // ===== Phase 1: gates + h update, 2 chunks of 256 n-cols per gate =====
        #pragma unroll 1
        for (int nc = 0; nc < 2; ++nc) {
            const int col = nc * 256 + ng2;

            ull aR[4], aZ[4], aN[4], aI[4];
            #pragma unroll
            for (int i = 0; i < 4; ++i) { aR[i] = 0; aZ[i] = 0; aN[i] = 0; aI[i] = 0; }

            // x contribution (K=128) -> aR, aZ, aI
            gemm3<Fdim, 32>(d_WihT + col, xbuf, mrow0, aR, aZ, aI);
            // h contribution (K=512) -> aR, aZ, aN
            gemm3<Hdim, 128>(d_WhhT + col, hc, mrow0, aR, aZ, aN);

            // epilogue: nonlinearity + h update on this thread's 4m x 2n patch
            const float2 br = *reinterpret_cast<const float2*>(&brz[col]);
            const float2 bz = *reinterpret_cast<const float2*>(&brz[Hdim + col]);
            const float2 bi = *reinterpret_cast<const float2*>(&bin[col]);
            const float2 bh = *reinterpret_cast<const float2*>(&bhn[col]);
            #pragma unroll
            for (int i = 0; i < 4; ++i) {
                const int m = mrow0 + i;
                float2 R = unpack2(aR[i]), Z = unpack2(aZ[i]);
                float2 N = unpack2(aN[i]), I = unpack2(aI[i]);
                float2 hp = *reinterpret_cast<const float2*>(&hc[m * Hdim + col]);

                float r0 = 1.f / (1.f + __expf(-(R.x + br.x)));
                float r1 = 1.f / (1.f + __expf(-(R.y + br.y)));
                float z0 = 1.f / (1.f + __expf(-(Z.x + bz.x)));
                float z1 = 1.f / (1.f + __expf(-(Z.y + bz.y)));
                float n0 = tanhf(I.x + bi.x + r0 * (N.x + bh.x));
                float n1 = tanhf(I.y + bi.y + r1 * (N.y + bh.y));
                float2 hv = make_float2((1.f - z0) * n0 + z0 * hp.x,
                                        (1.f - z1) * n1 + z1 * hp.y);
                *reinterpret_cast<float2*>(&hn[m * Hdim + col]) = hv;
            }
        }
        __syncthreads();   // hn complete

        // ===== Phase 2: x_new = h_new @ fc_w^T + fc_b (A/B pipelined, 2m x 2f) =====
        {
            ull acc[2] = {0ull, 0ull};
            ull fA[8], fB[8];
            const float* fw = d_FcwT + f0;

            #pragma unroll
            for (int kk = 0; kk < 8; ++kk)
                fA[kk] = ld64(fw + (size_t)kk * Fdim);

            #pragma unroll 1
            for (int it = 0; it < 64; it += 2) {
                #pragma unroll
                for (int kk = 0; kk < 8; ++kk)
                    fB[kk] = ld64(fw + (size_t)((it + 1) * 8 + kk) * Fdim);
                {
                    const int k0 = it * 8;
                    float4 av[2][2];
                    #pragma unroll
                    for (int i = 0; i < 2; ++i) {
                        const float* row = hn + (size_t)(mh * 2 + i) * Hdim + k0;
                        av[i][0] = *reinterpret_cast<const float4*>(row);
                        av[i][1] = *reinterpret_cast<const float4*>(row + 4);
                    }
                    #pragma unroll
                    for (int kk = 0; kk < 8; ++kk) {
                        #pragma unroll
                        for (int i = 0; i < 2; ++i) {
                            ull a2 = bcast2(
                                reinterpret_cast<const float*>(&av[i][kk >> 2])[kk & 3]);
                            fma2(acc[i], a2, fA[kk]);
                        }
                    }
                }
                {
                    const int nx = (it + 2 < 64) ? (it + 2) : it;
                    #pragma unroll
                    for (int kk = 0; kk < 8; ++kk)
                        fA[kk] = ld64(fw + (size_t)(nx * 8 + kk) * Fdim);
                }
                {
                    const int k0 = (it + 1) * 8;
                    float4 av[2][2];
                    #pragma unroll
                    for (int i = 0; i < 2; ++i) {
                        const float* row = hn + (size_t)(mh * 2 + i) * Hdim + k0;
                        av[i][0] = *reinterpret_cast<const float4*>(row);
                        av[i][1] = *reinterpret_cast<const float4*>(row + 4);
                    }
                    #pragma unroll
                    for (int kk = 0; kk < 8; ++kk) {
                        #pragma unroll
                        for (int i = 0; i < 2; ++i) {
                            ull a2 = bcast2(
                                reinterpret_cast<const float*>(&av[i][kk >> 2])[kk & 3]);
                            fma2(acc[i], a2, fB[kk]);
                        }
                    }
                }
            }

            const int trow = Tlen - 1 - s;   // reference reverses time at the end
            const float2 fb2 = *reinterpret_cast<const float2*>(&fcb[f0]);
            #pragma unroll
            for (int i = 0; i < 2; ++i) {
                const int m = mh * 2 + i;
                float2 v = unpack2(acc[i]);
                const float v0 = v.x + fb2.x;
                const float v1 = v.y + fb2.y;
                *reinterpret_cast<float2*>(&xbuf[m * Fdim + f0]) = make_float2(v0, v1);
                *reinterpret_cast<float2*>(
                    &out[((size_t)(m0 + m) * Tlen + trow) * Fdim + f0]) =
                    make_float2(v0, v1);
            }
        }
        __syncthreads();   // xbuf complete before next step's phase 1

        float* tmp = hc; hc = hn; hn = tmp;
    }
}

extern "C" void kernel_launch(void* const* d_in, const int* in_sizes, int n_in,
                              void* d_out, int out_size) {
    const float* hidden = (const float*)d_in[0];
    const float* w_ih   = (const float*)d_in[1];
    const float* w_hh   = (const float*)d_in[2];
    const float* b_ih   = (const float*)d_in[3];
    const float* b_hh   = (const float*)d_in[4];
    const float* fc_w   = (const float*)d_in[5];
    const float* fc_b   = (const float*)d_in[6];
    float* out = (float*)d_out;

    const int total = Hdim * G3H + Fdim * G3H + Hdim * Fdim;
    gru_setup_kernel<<<(total + 255) / 256, 256>>>(w_ih, w_hh, fc_w);

    const int smem_bytes =
        (2 * Mtile * Hdim + Mtile * Fdim + 2 * Hdim + Hdim + Hdim + Fdim) * (int)sizeof(float);
    cudaFuncSetAttribute(gru_kernel, cudaFuncAttributeMaxDynamicSharedMemorySize, smem_bytes);
    gru_kernel<<<Bsz / Mtile, NTHREADS, smem_bytes>>>(hidden, b_ih, b_hh, fc_b, out);
}

// round 10
// speedup vs baseline: 1.7787x; 1.7787x over previous
#include <cuda_runtime.h>
#include <math.h>

#define Bsz   2048
#define Fdim  128
#define Hdim  512
#define Tlen  96
#define G3H   1536
#define Mtile 16
#define NTHREADS 256

typedef unsigned long long ull;

// Transposed weights (k-major) in device scratch, ~4MB, L2-resident.
__device__ __align__(16) float d_WhhT[Hdim * G3H];  // [k][n] k<512, n<1536
__device__ __align__(16) float d_WihT[Fdim * G3H];  // [k][n] k<128, n<1536
__device__ __align__(16) float d_FcwT[Hdim * Fdim]; // [k][f] k<512, f<128

// ---- packed f32x2 helpers ----
__device__ __forceinline__ ull bcast2(float a) {
    ull r; unsigned int u = __float_as_uint(a);
    asm("mov.b64 %0, {%1, %1};" : "=l"(r) : "r"(u));
    return r;
}
__device__ __forceinline__ void fma2(ull& d, ull a, ull b) {
    asm("fma.rn.f32x2 %0, %1, %2, %0;" : "+l"(d) : "l"(a), "l"(b));
}
__device__ __forceinline__ float2 unpack2(ull v) {
    unsigned int lo, hi;
    asm("mov.b64 {%0, %1}, %2;" : "=r"(lo), "=r"(hi) : "l"(v));
    return make_float2(__uint_as_float(lo), __uint_as_float(hi));
}
__device__ __forceinline__ ull ld64(const float* p) {
    return *reinterpret_cast<const ull*>(p);
}

// One-time weight transpose
__global__ void gru_setup_kernel(const float* __restrict__ w_ih,
                                 const float* __restrict__ w_hh,
                                 const float* __restrict__ fc_w) {
    int idx = blockIdx.x * blockDim.x + threadIdx.x;
    if (idx < Hdim * G3H) {
        int k = idx / G3H, n = idx - k * G3H;
        d_WhhT[idx] = w_hh[n * Hdim + k];
    }
    int i2 = idx - Hdim * G3H;
    if (i2 >= 0 && i2 < Fdim * G3H) {
        int k = i2 / G3H, n = i2 - k * G3H;
        d_WihT[i2] = w_ih[n * Fdim + k];
    }
    int i3 = idx - Hdim * G3H - Fdim * G3H;
    if (i3 >= 0 && i3 < Hdim * Fdim) {
        int k = i3 / Fdim, f = i3 - k * Fdim;
        d_FcwT[i3] = fc_w[f * Hdim + k];
    }
}

// One 4-k compute stage of the 3-gate GEMM: 16 m-rows x 2 cols x 3 gates.
template<int LD>
__device__ __forceinline__ void g3_stage(
    const ull (&w)[4][3], const float* __restrict__ in, int k0,
    ull (&aR)[16], ull (&aZ)[16], ull (&aX)[16])
{
    float2 av[16];
    #pragma unroll
    for (int m = 0; m < 16; ++m)
        av[m] = *reinterpret_cast<const float2*>(&in[m * LD + k0]);
    #pragma unroll
    for (int kk = 0; kk < 2; ++kk) {
        ull wr = w[kk][0], wz = w[kk][1], wn = w[kk][2];
        #pragma unroll
        for (int m = 0; m < 16; ++m) {
            ull a2 = bcast2(kk ? av[m].y : av[m].x);
            fma2(aR[m], a2, wr); fma2(aZ[m], a2, wz); fma2(aX[m], a2, wn);
        }
    }
    #pragma unroll
    for (int m = 0; m < 16; ++m)
        av[m] = *reinterpret_cast<const float2*>(&in[m * LD + k0 + 2]);
    #pragma unroll
    for (int kk = 2; kk < 4; ++kk) {
        ull wr = w[kk][0], wz = w[kk][1], wn = w[kk][2];
        #pragma unroll
        for (int m = 0; m < 16; ++m) {
            ull a2 = bcast2((kk & 1) ? av[m].y : av[m].x);
            fma2(aR[m], a2, wr); fma2(aZ[m], a2, wz); fma2(aX[m], a2, wn);
        }
    }
}

// Split-K 3-gate GEMM: this thread handles K-slice [kbeg, kbeg+NST*4),
// accumulating 16 m-rows x 2 n-cols x 3 gates. Register A/B weight ping-pong.
template<int LD, int NST>   // NST even
__device__ __forceinline__ void gemm3_split(
    const float* __restrict__ wbase,   // weight[k][gate-col]; row k at wbase + k*G3H
    const float* __restrict__ in, int kbeg,
    ull (&aR)[16], ull (&aZ)[16], ull (&aX)[16])
{
    ull wA[4][3], wB[4][3];
    const float* wk = wbase + (size_t)kbeg * G3H;

    #pragma unroll
    for (int kk = 0; kk < 4; ++kk) {
        const float* w = wk + (size_t)kk * G3H;
        wA[kk][0] = ld64(w); wA[kk][1] = ld64(w + 512); wA[kk][2] = ld64(w + 1024);
    }

    #pragma unroll 1
    for (int it = 0; it < NST; it += 2) {
        {   // prefetch B <- stage it+1
            const float* wr = wk + (size_t)(it + 1) * 4 * G3H;
            #pragma unroll
            for (int kk = 0; kk < 4; ++kk) {
                const float* w = wr + (size_t)kk * G3H;
                wB[kk][0] = ld64(w); wB[kk][1] = ld64(w + 512); wB[kk][2] = ld64(w + 1024);
            }
        }
        g3_stage<LD>(wA, in, kbeg + it * 4, aR, aZ, aX);
        {   // prefetch A <- stage it+2 (clamped; final prefetch is dead)
            const int nx = (it + 2 < NST) ? (it + 2) : it;
            const float* wr = wk + (size_t)nx * 4 * G3H;
            #pragma unroll
            for (int kk = 0; kk < 4; ++kk) {
                const float* w = wr + (size_t)kk * G3H;
                wA[kk][0] = ld64(w); wA[kk][1] = ld64(w + 512); wA[kk][2] = ld64(w + 1024);
            }
        }
        g3_stage<LD>(wB, in, kbeg + (it + 1) * 4, aR, aZ, aX);
    }
}

// Split-K fc GEMM stage: 16 m-rows x 2 f-cols.
__device__ __forceinline__ void gf_stage(
    const ull (&w)[4], const float* __restrict__ in, int k0, ull (&aF)[16])
{
    float2 av[16];
    #pragma unroll
    for (int m = 0; m < 16; ++m)
        av[m] = *reinterpret_cast<const float2*>(&in[m * Hdim + k0]);
    #pragma unroll
    for (int kk = 0; kk < 2; ++kk) {
        #pragma unroll
        for (int m = 0; m < 16; ++m)
            fma2(aF[m], bcast2(kk ? av[m].y : av[m].x), w[kk]);
    }
    #pragma unroll
    for (int m = 0; m < 16; ++m)
        av[m] = *reinterpret_cast<const float2*>(&in[m * Hdim + k0 + 2]);
    #pragma unroll
    for (int kk = 2; kk < 4; ++kk) {
        #pragma unroll
        for (int m = 0; m < 16; ++m)
            fma2(aF[m], bcast2((kk & 1) ? av[m].y : av[m].x), w[kk]);
    }
}

template<int NST>
__device__ __forceinline__ void gemmF_split(
    const float* __restrict__ wbase, const float* __restrict__ in,
    int kbeg, ull (&aF)[16])
{
    ull wA[4], wB[4];
    const float* wk = wbase + (size_t)kbeg * Fdim;
    #pragma unroll
    for (int kk = 0; kk < 4; ++kk) wA[kk] = ld64(wk + (size_t)kk * Fdim);

    #pragma unroll 1
    for (int it = 0; it < NST; it += 2) {
        #pragma unroll
        for (int kk = 0; kk < 4; ++kk)
            wB[kk] = ld64(wk + (size_t)((it + 1) * 4 + kk) * Fdim);
        gf_stage(wA, in, kbeg + it * 4, aF);
        {
            const int nx = (it + 2 < NST) ? (it + 2) : it;
            #pragma unroll
            for (int kk = 0; kk < 4; ++kk)
                wA[kk] = ld64(wk + (size_t)(nx * 4 + kk) * Fdim);
        }
        gf_stage(wB, in, kbeg + (it + 1) * 4, aF);
    }
}

__global__ __launch_bounds__(NTHREADS, 1)
void gru_kernel(const float* __restrict__ hidden,
                const float* __restrict__ b_ih,
                const float* __restrict__ b_hh,
                const float* __restrict__ fc_b,
                float* __restrict__ out) {
    extern __shared__ float smem[];
    float* hbufA = smem;                          // 16*512
    float* hbufB = hbufA + Mtile * Hdim;          // 16*512
    float* xbuf  = hbufB + Mtile * Hdim;          // 16*128
    float* brz   = xbuf + Mtile * Fdim;           // 1024
    float* bin   = brz + 2 * Hdim;                // 512
    float* bhn   = bin + Hdim;                    // 512
    float* fcb   = bhn + Hdim;                    // 128
    float* part  = fcb + Fdim;                    // 16 slots * 16 m * 128 cols = 32768

    const int tid = threadIdx.x;
    const int m0  = blockIdx.x * Mtile;

    for (int i = tid; i < Mtile * Hdim; i += NTHREADS) hbufA[i] = hidden[m0 * Hdim + i];
    for (int i = tid; i < Mtile * Fdim; i += NTHREADS) xbuf[i] = 0.f;
    for (int i = tid; i < 2 * Hdim; i += NTHREADS)     brz[i] = b_ih[i] + b_hh[i];
    for (int i = tid; i < Hdim; i += NTHREADS) {
        bin[i] = b_ih[2 * Hdim + i];
        bhn[i] = b_hh[2 * Hdim + i];
    }
    for (int i = tid; i < Fdim; i += NTHREADS)         fcb[i] = fc_b[i];
    __syncthreads();

    // Split-K mapping: kg = K-slice group (0..3), ng2 = 2 cols of the 128-col chunk.
    const int kg  = tid >> 6;             // 0..3
    const int ng2 = (tid & 63) * 2;       // 0..126
    // Epilogue mapping: 4 m-rows per thread, same ng2 cols.
    const int mg4 = (tid >> 6) * 4;

    float* hc = hbufA;
    float* hn = hbufB;

    for (int s = 0; s < Tlen; ++s) {
        // ===== Phase 1: gates + h update, 4 chunks of 128 n-cols per gate =====
        #pragma unroll 1
        for (int nc = 0; nc < 4; ++nc) {
            const int col = nc * 128 + ng2;    // within-gate column

            ull aR[16], aZ[16], aX[16];
            #pragma unroll
            for (int m = 0; m < 16; ++m) { aR[m] = 0; aZ[m] = 0; aX[m] = 0; }

            // hh contribution: this kg handles k in [kg*128, kg*128+128)
            gemm3_split<Hdim, 32>(d_WhhT + col, hc, kg * 128, aR, aZ, aX);

            // dump hh partials (r, z, h_n)
            #pragma unroll
            for (int m = 0; m < 16; ++m) {
                *reinterpret_cast<ull*>(&part[((kg)     * 16 + m) * 128 + ng2]) = aR[m];
                *reinterpret_cast<ull*>(&part[((4 + kg) * 16 + m) * 128 + ng2]) = aZ[m];
                *reinterpret_cast<ull*>(&part[((8 + kg) * 16 + m) * 128 + ng2]) = aX[m];
            }

            // ih contribution: k in [kg*32, kg*32+32)
            #pragma unroll
            for (int m = 0; m < 16; ++m) { aR[m] = 0; aZ[m] = 0; aX[m] = 0; }
            gemm3_split<Fdim, 8>(d_WihT + col, xbuf, kg * 32, aR, aZ, aX);

            // dump i_n; fold ih r/z into the hh r/z slots (same thread owns them)
            #pragma unroll
            for (int m = 0; m < 16; ++m) {
                *reinterpret_cast<ull*>(&part[((12 + kg) * 16 + m) * 128 + ng2]) = aX[m];
                float2* pr = reinterpret_cast<float2*>(&part[(kg * 16 + m) * 128 + ng2]);
                float2 cr = unpack2(aR[m]);
                float2 vr = *pr; pr->x = vr.x + cr.x; pr->y = vr.y + cr.y;
                float2* pz = reinterpret_cast<float2*>(&part[((4 + kg) * 16 + m) * 128 + ng2]);
                float2 cz = unpack2(aZ[m]);
                float2 vz = *pz; pz->x = vz.x + cz.x; pz->y = vz.y + cz.y;
            }
            __syncthreads();

            // epilogue: reduce 4 kg slices, apply gates; 4 m-rows x 2 cols per thread
            const float2 br = *reinterpret_cast<const float2*>(&brz[col]);
            const float2 bz = *reinterpret_cast<const float2*>(&brz[Hdim + col]);
            const float2 bi = *reinterpret_cast<const float2*>(&bin[col]);
            const float2 bh = *reinterpret_cast<const float2*>(&bhn[col]);
            #pragma unroll
            for (int i = 0; i < 4; ++i) {
                const int m = mg4 + i;
                float2 R = make_float2(0.f, 0.f), Z = R, NH = R, NI = R;
                #pragma unroll
                for (int g = 0; g < 4; ++g) {
                    float2 v;
                    v = *reinterpret_cast<const float2*>(&part[((g)      * 16 + m) * 128 + ng2]);
                    R.x += v.x; R.y += v.y;
                    v = *reinterpret_cast<const float2*>(&part[((4 + g)  * 16 + m) * 128 + ng2]);
                    Z.x += v.x; Z.y += v.y;
                    v = *reinterpret_cast<const float2*>(&part[((8 + g)  * 16 + m) * 128 + ng2]);
                    NH.x += v.x; NH.y += v.y;
                    v = *reinterpret_cast<const float2*>(&part[((12 + g) * 16 + m) * 128 + ng2]);
                    NI.x += v.x; NI.y += v.y;
                }
                float2 hp = *reinterpret_cast<const float2*>(&hc[m * Hdim + col]);
                float r0 = 1.f / (1.f + __expf(-(R.x + br.x)));
                float r1 = 1.f / (1.f + __expf(-(R.y + br.y)));
                float z0 = 1.f / (1.f + __expf(-(Z.x + bz.x)));
                float z1 = 1.f / (1.f + __expf(-(Z.y + bz.y)));
                float n0 = tanhf(NI.x + bi.x + r0 * (NH.x + bh.x));
                float n1 = tanhf(NI.y + bi.y + r1 * (NH.y + bh.y));
                *reinterpret_cast<float2*>(&hn[m * Hdim + col]) =
                    make_float2((1.f - z0) * n0 + z0 * hp.x,
                                (1.f - z1) * n1 + z1 * hp.y);
            }
            __syncthreads();   // partials consumed; hn chunk visible
        }

        // ===== Phase 2: x_new = h_new @ fc_w^T + fc_b (split-K) =====
        {
            ull aF[16];
            #pragma unroll
            for (int m = 0; m < 16; ++m) aF[m] = 0;
            gemmF_split<32>(d_FcwT + ng2, hn, kg * 128, aF);

            #pragma unroll
            for (int m = 0; m < 16; ++m)
                *reinterpret_cast<ull*>(&part[(kg * 16 + m) * 128 + ng2]) = aF[m];
            __syncthreads();

            const int trow = Tlen - 1 - s;   // reference reverses time at the end
            const float2 fb2 = *reinterpret_cast<const float2*>(&fcb[ng2]);
            #pragma unroll
            for (int i = 0; i < 4; ++i) {
                const int m = mg4 + i;
                float2 F = make_float2(0.f, 0.f);
                #pragma unroll
                for (int g = 0; g < 4; ++g) {
                    float2 v = *reinterpret_cast<const float2*>(
                        &part[(g * 16 + m) * 128 + ng2]);
                    F.x += v.x; F.y += v.y;
                }
                const float v0 = F.x + fb2.x;
                const float v1 = F.y + fb2.y;
                *reinterpret_cast<float2*>(&xbuf[m * Fdim + ng2]) = make_float2(v0, v1);
                *reinterpret_cast<float2*>(
                    &out[((size_t)(m0 + m) * Tlen + trow) * Fdim + ng2]) =
                    make_float2(v0, v1);
            }
            __syncthreads();
        }

        float* tmp = hc; hc = hn; hn = tmp;
    }
}

extern "C" void kernel_launch(void* const* d_in, const int* in_sizes, int n_in,
                              void* d_out, int out_size) {
    const float* hidden = (const float*)d_in[0];
    const float* w_ih   = (const float*)d_in[1];
    const float* w_hh   = (const float*)d_in[2];
    const float* b_ih   = (const float*)d_in[3];
    const float* b_hh   = (const float*)d_in[4];
    const float* fc_w   = (const float*)d_in[5];
    const float* fc_b   = (const float*)d_in[6];
    float* out = (float*)d_out;

    const int total = Hdim * G3H + Fdim * G3H + Hdim * Fdim;
    gru_setup_kernel<<<(total + 255) / 256, 256>>>(w_ih, w_hh, fc_w);

    const int smem_floats =
        2 * Mtile * Hdim + Mtile * Fdim + 2 * Hdim + Hdim + Hdim + Fdim +
        16 * 16 * 128;
    const int smem_bytes = smem_floats * (int)sizeof(float);
    cudaFuncSetAttribute(gru_kernel, cudaFuncAttributeMaxDynamicSharedMemorySize, smem_bytes);
    gru_kernel<<<Bsz / Mtile, NTHREADS, smem_bytes>>>(hidden, b_ih, b_hh, fc_b, out);
}

// round 11
// speedup vs baseline: 1.9841x; 1.1155x over previous
#include <cuda_runtime.h>
#include <math.h>

#define Bsz   2048
#define Fdim  128
#define Hdim  512
#define Tlen  96
#define G3H   1536
#define Mtile 16
#define NTHREADS 256

typedef unsigned long long ull;
typedef ulonglong2 ull2;

// Transposed weights (k-major) in device scratch, ~4MB, L2-resident.
__device__ __align__(16) float d_WhhT[Hdim * G3H];  // [k][n] k<512, n<1536
__device__ __align__(16) float d_WihT[Fdim * G3H];  // [k][n] k<128, n<1536
__device__ __align__(16) float d_FcwT[Hdim * Fdim]; // [k][f] k<512, f<128

// ---- packed f32x2 helpers ----
__device__ __forceinline__ ull bcast2(float a) {
    ull r; unsigned int u = __float_as_uint(a);
    asm("mov.b64 %0, {%1, %1};" : "=l"(r) : "r"(u));
    return r;
}
__device__ __forceinline__ void fma2(ull& d, ull a, ull b) {
    asm("fma.rn.f32x2 %0, %1, %2, %0;" : "+l"(d) : "l"(a), "l"(b));
}
__device__ __forceinline__ float2 unpack2(ull v) {
    unsigned int lo, hi;
    asm("mov.b64 {%0, %1}, %2;" : "=r"(lo), "=r"(hi) : "l"(v));
    return make_float2(__uint_as_float(lo), __uint_as_float(hi));
}
__device__ __forceinline__ ull ld64(const float* p) {
    return *reinterpret_cast<const ull*>(p);
}
__device__ __forceinline__ float fast_sigmoid(float x) {
    return __fdividef(1.f, 1.f + __expf(-x));
}
__device__ __forceinline__ float fast_tanh(float x) {
    float t = __expf(2.f * x);
    return 1.f - __fdividef(2.f, t + 1.f);
}

// One-time weight transpose
__global__ void gru_setup_kernel(const float* __restrict__ w_ih,
                                 const float* __restrict__ w_hh,
                                 const float* __restrict__ fc_w) {
    int idx = blockIdx.x * blockDim.x + threadIdx.x;
    if (idx < Hdim * G3H) {
        int k = idx / G3H, n = idx - k * G3H;
        d_WhhT[idx] = w_hh[n * Hdim + k];
    }
    int i2 = idx - Hdim * G3H;
    if (i2 >= 0 && i2 < Fdim * G3H) {
        int k = i2 / G3H, n = i2 - k * G3H;
        d_WihT[i2] = w_ih[n * Fdim + k];
    }
    int i3 = idx - Hdim * G3H - Fdim * G3H;
    if (i3 >= 0 && i3 < Hdim * Fdim) {
        int k = i3 / Fdim, f = i3 - k * Fdim;
        d_FcwT[i3] = fc_w[f * Hdim + k];
    }
}

// Load one 2-kk weight stage: 3 gates x 4 cols per kk (ld128 each).
__device__ __forceinline__ void ldw3(ull2 (&wb)[2][3], const float* wk, int stage) {
    const float* p = wk + (size_t)stage * 2 * G3H;
    #pragma unroll
    for (int kk = 0; kk < 2; ++kk) {
        const float* q = p + (size_t)kk * G3H;
        wb[kk][0] = *reinterpret_cast<const ull2*>(q);
        wb[kk][1] = *reinterpret_cast<const ull2*>(q + 512);
        wb[kk][2] = *reinterpret_cast<const ull2*>(q + 1024);
    }
}

// Compute one 2-kk stage: 8 m-rows x 4 n-cols x 3 gates.
template<int LD>
__device__ __forceinline__ void g3_stage(
    const ull2 (&w)[2][3], const float* __restrict__ in, int k0, int m0,
    ull (&aR)[8][2], ull (&aZ)[8][2], ull (&aX)[8][2])
{
    float2 av[8];
    #pragma unroll
    for (int m = 0; m < 8; ++m)
        av[m] = *reinterpret_cast<const float2*>(&in[(m0 + m) * LD + k0]);
    #pragma unroll
    for (int kk = 0; kk < 2; ++kk) {
        #pragma unroll
        for (int m = 0; m < 8; ++m) {
            ull a2 = bcast2(kk ? av[m].y : av[m].x);
            fma2(aR[m][0], a2, w[kk][0].x); fma2(aR[m][1], a2, w[kk][0].y);
            fma2(aZ[m][0], a2, w[kk][1].x); fma2(aZ[m][1], a2, w[kk][1].y);
            fma2(aX[m][0], a2, w[kk][2].x); fma2(aX[m][1], a2, w[kk][2].y);
        }
    }
}

// Split-K 3-gate GEMM over this thread's K-slice, register A/B ping-pong.
template<int LD, int NST>   // NST = K_slice/2, even
__device__ __forceinline__ void gemm3_split(
    const float* __restrict__ wbase,   // WT + colbase
    const float* __restrict__ in, int kbeg, int m0,
    ull (&aR)[8][2], ull (&aZ)[8][2], ull (&aX)[8][2])
{
    ull2 wA[2][3], wB[2][3];
    const float* wk = wbase + (size_t)kbeg * G3H;
    ldw3(wA, wk, 0);
    #pragma unroll 1
    for (int it = 0; it < NST; it += 2) {
        ldw3(wB, wk, it + 1);
        g3_stage<LD>(wA, in, kbeg + it * 2, m0, aR, aZ, aX);
        ldw3(wA, wk, (it + 2 < NST) ? it + 2 : it);
        g3_stage<LD>(wB, in, kbeg + (it + 1) * 2, m0, aR, aZ, aX);
    }
}

// ---- fc GEMM (phase 2), 16m x 2f per thread, split-K ----
__device__ __forceinline__ void gf_stage(
    const ull (&w)[4], const float* __restrict__ in, int k0, ull (&aF)[16])
{
    float2 av[16];
    #pragma unroll
    for (int m = 0; m < 16; ++m)
        av[m] = *reinterpret_cast<const float2*>(&in[m * Hdim + k0]);
    #pragma unroll
    for (int kk = 0; kk < 2; ++kk) {
        #pragma unroll
        for (int m = 0; m < 16; ++m)
            fma2(aF[m], bcast2(kk ? av[m].y : av[m].x), w[kk]);
    }
    #pragma unroll
    for (int m = 0; m < 16; ++m)
        av[m] = *reinterpret_cast<const float2*>(&in[m * Hdim + k0 + 2]);
    #pragma unroll
    for (int kk = 2; kk < 4; ++kk) {
        #pragma unroll
        for (int m = 0; m < 16; ++m)
            fma2(aF[m], bcast2((kk & 1) ? av[m].y : av[m].x), w[kk]);
    }
}

template<int NST>
__device__ __forceinline__ void gemmF_split(
    const float* __restrict__ wbase, const float* __restrict__ in,
    int kbeg, ull (&aF)[16])
{
    ull wA[4], wB[4];
    const float* wk = wbase + (size_t)kbeg * Fdim;
    #pragma unroll
    for (int kk = 0; kk < 4; ++kk) wA[kk] = ld64(wk + (size_t)kk * Fdim);
    #pragma unroll 1
    for (int it = 0; it < NST; it += 2) {
        #pragma unroll
        for (int kk = 0; kk < 4; ++kk)
            wB[kk] = ld64(wk + (size_t)((it + 1) * 4 + kk) * Fdim);
        gf_stage(wA, in, kbeg + it * 4, aF);
        {
            const int nx = (it + 2 < NST) ? (it + 2) : it;
            #pragma unroll
            for (int kk = 0; kk < 4; ++kk)
                wA[kk] = ld64(wk + (size_t)(nx * 4 + kk) * Fdim);
        }
        gf_stage(wB, in, kbeg + (it + 1) * 4, aF);
    }
}

__global__ __launch_bounds__(NTHREADS, 1)
void gru_kernel(const float* __restrict__ hidden,
                const float* __restrict__ b_ih,
                const float* __restrict__ b_hh,
                const float* __restrict__ fc_b,
                float* __restrict__ out) {
    extern __shared__ float smem[];
    float* hbufA = smem;                          // 16*512
    float* hbufB = hbufA + Mtile * Hdim;          // 16*512
    float* xbuf  = hbufB + Mtile * Hdim;          // 16*128
    float* brz   = xbuf + Mtile * Fdim;           // 1024
    float* bin   = brz + 2 * Hdim;                // 512
    float* bhn   = bin + Hdim;                    // 512
    float* fcb   = bhn + Hdim;                    // 128
    float* part  = fcb + Fdim;                    // 16 slots * 16 m * 128 cols

    const int tid = threadIdx.x;
    const int m0cta = blockIdx.x * Mtile;

    for (int i = tid; i < Mtile * Hdim; i += NTHREADS) hbufA[i] = hidden[m0cta * Hdim + i];
    for (int i = tid; i < Mtile * Fdim; i += NTHREADS) xbuf[i] = 0.f;
    for (int i = tid; i < 2 * Hdim; i += NTHREADS)     brz[i] = b_ih[i] + b_hh[i];
    for (int i = tid; i < Hdim; i += NTHREADS) {
        bin[i] = b_ih[2 * Hdim + i];
        bhn[i] = b_hh[2 * Hdim + i];
    }
    for (int i = tid; i < Fdim; i += NTHREADS)         fcb[i] = fc_b[i];
    __syncthreads();

    // Phase-1 mapping: [2 mg][4 kg][32 ng4]
    const int mg   = tid >> 7;            // 0..1
    const int kg   = (tid >> 5) & 3;      // 0..3
    const int ng4  = tid & 31;            // 0..31
    const int col4 = ng4 * 4;
    const int m0   = mg * 8;
    const int khh  = kg * 128;
    const int kih  = kg * 32;
    // Epilogue / phase-2 mapping: [4 groups of 4 m][64 ng2]
    const int mg4  = (tid >> 6) * 4;
    const int ng2  = (tid & 63) * 2;
    const int kg2  = tid >> 6;            // phase-2 K-slice group

    float* hc = hbufA;
    float* hn = hbufB;

    for (int s = 0; s < Tlen; ++s) {
        // ===== Phase 1: gates + h update, 4 chunks of 128 n-cols per gate =====
        #pragma unroll 1
        for (int nc = 0; nc < 4; ++nc) {
            const int colbase = nc * 128 + col4;

            ull aR[8][2], aZ[8][2], aX[8][2];
            #pragma unroll
            for (int m = 0; m < 8; ++m) {
                aR[m][0] = 0; aR[m][1] = 0; aZ[m][0] = 0; aZ[m][1] = 0;
                aX[m][0] = 0; aX[m][1] = 0;
            }

            // ih contribution first: k in [kg*32, kg*32+32)
            gemm3_split<Fdim, 16>(d_WihT + colbase, xbuf, kih, m0, aR, aZ, aX);

            // dump i_n partials; keep r/z live in registers
            #pragma unroll
            for (int m = 0; m < 8; ++m) {
                ull2 v; v.x = aX[m][0]; v.y = aX[m][1];
                *reinterpret_cast<ull2*>(
                    &part[((12 + kg) * 16 + m0 + m) * 128 + col4]) = v;
                aX[m][0] = 0; aX[m][1] = 0;
            }

            // hh contribution: k in [kg*128, kg*128+128)
            gemm3_split<Hdim, 64>(d_WhhT + colbase, hc, khh, m0, aR, aZ, aX);

            // dump r, z, h_n partials
            #pragma unroll
            for (int m = 0; m < 8; ++m) {
                ull2 v;
                v.x = aR[m][0]; v.y = aR[m][1];
                *reinterpret_cast<ull2*>(&part[((kg)     * 16 + m0 + m) * 128 + col4]) = v;
                v.x = aZ[m][0]; v.y = aZ[m][1];
                *reinterpret_cast<ull2*>(&part[((4 + kg) * 16 + m0 + m) * 128 + col4]) = v;
                v.x = aX[m][0]; v.y = aX[m][1];
                *reinterpret_cast<ull2*>(&part[((8 + kg) * 16 + m0 + m) * 128 + col4]) = v;
            }
            __syncthreads();

            // epilogue: reduce 4 kg slices, apply gates; 4 m x 2 cols per thread
            const int col = nc * 128 + ng2;
            const float2 br = *reinterpret_cast<const float2*>(&brz[col]);
            const float2 bz = *reinterpret_cast<const float2*>(&brz[Hdim + col]);
            const float2 bi = *reinterpret_cast<const float2*>(&bin[col]);
            const float2 bh = *reinterpret_cast<const float2*>(&bhn[col]);
            #pragma unroll
            for (int i = 0; i < 4; ++i) {
                const int m = mg4 + i;
                float2 R = make_float2(0.f, 0.f), Z = R, NH = R, NI = R;
                #pragma unroll
                for (int g = 0; g < 4; ++g) {
                    float2 v;
                    v = *reinterpret_cast<const float2*>(&part[((g)      * 16 + m) * 128 + ng2]);
                    R.x += v.x; R.y += v.y;
                    v = *reinterpret_cast<const float2*>(&part[((4 + g)  * 16 + m) * 128 + ng2]);
                    Z.x += v.x; Z.y += v.y;
                    v = *reinterpret_cast<const float2*>(&part[((8 + g)  * 16 + m) * 128 + ng2]);
                    NH.x += v.x; NH.y += v.y;
                    v = *reinterpret_cast<const float2*>(&part[((12 + g) * 16 + m) * 128 + ng2]);
                    NI.x += v.x; NI.y += v.y;
                }
                float2 hp = *reinterpret_cast<const float2*>(&hc[m * Hdim + col]);
                float r0 = fast_sigmoid(R.x + br.x);
                float r1 = fast_sigmoid(R.y + br.y);
                float z0 = fast_sigmoid(Z.x + bz.x);
                float z1 = fast_sigmoid(Z.y + bz.y);
                float n0 = fast_tanh(NI.x + bi.x + r0 * (NH.x + bh.x));
                float n1 = fast_tanh(NI.y + bi.y + r1 * (NH.y + bh.y));
                *reinterpret_cast<float2*>(&hn[m * Hdim + col]) =
                    make_float2((1.f - z0) * n0 + z0 * hp.x,
                                (1.f - z1) * n1 + z1 * hp.y);
            }
            __syncthreads();   // partials consumed; hn chunk visible
        }

        // ===== Phase 2: x_new = h_new @ fc_w^T + fc_b (split-K) =====
        {
            ull aF[16];
            #pragma unroll
            for (int m = 0; m < 16; ++m) aF[m] = 0;
            gemmF_split<32>(d_FcwT + ng2, hn, kg2 * 128, aF);

            #pragma unroll
            for (int m = 0; m < 16; ++m)
                *reinterpret_cast<ull*>(&part[(kg2 * 16 + m) * 128 + ng2]) = aF[m];
            __syncthreads();

            const int trow = Tlen - 1 - s;   // reference reverses time at the end
            const float2 fb2 = *reinterpret_cast<const float2*>(&fcb[ng2]);
            #pragma unroll
            for (int i = 0; i < 4; ++i) {
                const int m = mg4 + i;
                float2 F = make_float2(0.f, 0.f);
                #pragma unroll
                for (int g = 0; g < 4; ++g) {
                    float2 v = *reinterpret_cast<const float2*>(
                        &part[(g * 16 + m) * 128 + ng2]);
                    F.x += v.x; F.y += v.y;
                }
                const float v0 = F.x + fb2.x;
                const float v1 = F.y + fb2.y;
                *reinterpret_cast<float2*>(&xbuf[m * Fdim + ng2]) = make_float2(v0, v1);
                *reinterpret_cast<float2*>(
                    &out[((size_t)(m0cta + m) * Tlen + trow) * Fdim + ng2]) =
                    make_float2(v0, v1);
            }
            __syncthreads();
        }

        float* tmp = hc; hc = hn; hn = tmp;
    }
}

extern "C" void kernel_launch(void* const* d_in, const int* in_sizes, int n_in,
                              void* d_out, int out_size) {
    const float* hidden = (const float*)d_in[0];
    const float* w_ih   = (const float*)d_in[1];
    const float* w_hh   = (const float*)d_in[2];
    const float* b_ih   = (const float*)d_in[3];
    const float* b_hh   = (const float*)d_in[4];
    const float* fc_w   = (const float*)d_in[5];
    const float* fc_b   = (const float*)d_in[6];
    float* out = (float*)d_out;

    const int total = Hdim * G3H + Fdim * G3H + Hdim * Fdim;
    gru_setup_kernel<<<(total + 255) / 256, 256>>>(w_ih, w_hh, fc_w);

    const int smem_floats =
        2 * Mtile * Hdim + Mtile * Fdim + 2 * Hdim + Hdim + Hdim + Fdim +
        16 * 16 * 128;
    const int smem_bytes = smem_floats * (int)sizeof(float);
    cudaFuncSetAttribute(gru_kernel, cudaFuncAttributeMaxDynamicSharedMemorySize, smem_bytes);
    gru_kernel<<<Bsz / Mtile, NTHREADS, smem_bytes>>>(hidden, b_ih, b_hh, fc_b, out);
}